// round 8
// baseline (speedup 1.0000x reference)
#include <cuda_runtime.h>
#include <cstdint>

// DTL loss: inputs [M,N] f32, targets [M] i32 -> scalar f32
//   pos = inputs[r, tgt[r]]
//   hard = top-num_hard of row with target masked to -inf
//   out = mean_r( (1-pos)^2 + 0.2 * mean((1+hard)^2) )
//
// One CTA per row. Threshold prefilter (x >= 2.0, target skipped inline),
// MLP-4 unrolled streaming pass. Exact selection on candidates via
// top-3-bit split + 8-bit radix refinement + rank select; exact global
// fallback when the guard fails. Double accumulation for numeric safety.

#define THREADS  256
#define CAP      1024
#define RANK_MAX 48
#define THRESH   2.0f      // f2key(2.0f) = 0xC0000000 -> bin 6
#define DELTA    0.2
#define MAXROWS  8192

__device__ double g_rows[MAXROWS];

__device__ __forceinline__ unsigned f2key(unsigned u) {
    // monotone map: larger float -> larger unsigned key
    return u ^ (((unsigned)((int)u >> 31)) | 0x80000000u);
}
__device__ __forceinline__ float key2f(unsigned k) {
    unsigned u = (k & 0x80000000u) ? (k ^ 0x80000000u) : ~k;
    return __uint_as_float(u);
}

__global__ void finalize_kernel(float* out, int m) {
    __shared__ double sm[256];
    double s = 0.0;
    for (int i = threadIdx.x; i < m; i += 256) s += g_rows[i];
    sm[threadIdx.x] = s;
    __syncthreads();
#pragma unroll
    for (int off = 128; off > 0; off >>= 1) {
        if (threadIdx.x < off) sm[threadIdx.x] += sm[threadIdx.x + off];
        __syncthreads();
    }
    if (threadIdx.x == 0) out[0] = (float)(sm[0] / (double)m);
}

__global__ void __launch_bounds__(THREADS) dtl_kernel(
    const float* __restrict__ inputs,
    const int*   __restrict__ targets,
    int n, int num_hard)
{
    __shared__ unsigned candA[CAP];
    __shared__ unsigned candB[CAP];
    __shared__ unsigned hist[256];
    __shared__ int    s_cnt, s_c7, s_cnt2, s_sel, s_k;
    __shared__ double warp_sums[THREADS / 32];

    const int row  = blockIdx.x;
    const int tid  = threadIdx.x;
    const int lane = tid & 31;
    const int wid  = tid >> 5;
    const float* rowp = inputs + (size_t)row * (size_t)n;
    const int tgt = targets[row];

    float pos_val = 0.0f;               // used by tid 0 only
    if (tid == 0) {
        s_cnt = 0; s_c7 = 0;
        pos_val = __ldg(rowp + tgt);
    }
    __syncthreads();

    // Alignment split: head scalars to 16B boundary, float4 body, tail.
    const int off4 = (int)(((uintptr_t)rowp >> 2) & 3u);
    int head = (4 - off4) & 3;
    if (head > n) head = n;
    const int nvec = (n - head) >> 2;
    const int nsca = n - 4 * nvec;       // head + tail scalars

    // ---------- Pass 1: MLP-4 stream; push values >= THRESH (skip target) --
    {
        const float4* vp = reinterpret_cast<const float4*>(rowp + head);

#define DTL_PROC(v, jj)                                                   \
        do {                                                              \
            float mx_ = fmaxf(fmaxf((v).x, (v).y), fmaxf((v).z, (v).w));  \
            if (mx_ >= THRESH) {                                          \
                const int base_ = head + 4 * (jj);                        \
                float e_[4] = {(v).x, (v).y, (v).z, (v).w};               \
                _Pragma("unroll")                                         \
                for (int q_ = 0; q_ < 4; q_++) {                          \
                    if (e_[q_] >= THRESH && (base_ + q_) != tgt) {        \
                        int p_ = atomicAdd(&s_cnt, 1);                    \
                        if (p_ < CAP) {                                   \
                            unsigned key_ = f2key(__float_as_uint(e_[q_]));\
                            candA[p_] = key_;                             \
                            if (key_ >= 0xE0000000u) atomicAdd(&s_c7, 1); \
                        }                                                 \
                    }                                                     \
                }                                                         \
            }                                                             \
        } while (0)

        int j = tid;
        for (; j + 3 * THREADS < nvec; j += 4 * THREADS) {
            float4 a = __ldg(vp + j);
            float4 b = __ldg(vp + j + THREADS);
            float4 c = __ldg(vp + j + 2 * THREADS);
            float4 d = __ldg(vp + j + 3 * THREADS);
            DTL_PROC(a, j);
            DTL_PROC(b, j + THREADS);
            DTL_PROC(c, j + 2 * THREADS);
            DTL_PROC(d, j + 3 * THREADS);
        }
        for (; j < nvec; j += THREADS) {
            float4 a = __ldg(vp + j);
            DTL_PROC(a, j);
        }
#undef DTL_PROC

        if (tid < nsca) {
            int col = (tid < head) ? tid : (4 * nvec + tid);
            float x = __ldg(rowp + col);
            if (x >= THRESH && col != tgt) {
                int p = atomicAdd(&s_cnt, 1);
                if (p < CAP) {
                    unsigned key = f2key(__float_as_uint(x));
                    candA[p] = key;
                    if (key >= 0xE0000000u) atomicAdd(&s_c7, 1);
                }
            }
        }
    }
    __syncthreads();

    const int c  = s_cnt;
    const int c7 = s_c7;
    double acc = 0.0;

    if (num_hard > 0 && c >= num_hard && c <= CAP) {
        // ---------- Common path: exact (top-k of negatives is in candA) ----
        const int sel = (num_hard <= c7) ? 7 : 6;
        if (tid == 0) {
            s_k    = (sel == 7) ? num_hard : (num_hard - c7);
            s_cnt2 = 0;
        }
        __syncthreads();

        // Split sweep: winners (bin > sel) summed, boundary bin compacted.
        for (int j = tid; j < c; j += THREADS) {
            unsigned key = candA[j];
            int b = (int)(key >> 29);
            if (b > sel) {
                double t = 1.0 + (double)key2f(key);
                acc += t * t;
            } else if (b == sel) {
                int p = atomicAdd(&s_cnt2, 1);
                candB[p] = key;
            }
        }
        __syncthreads();

        int cc = s_cnt2;
        // ---------- 8-bit radix refinement ----------
        unsigned* src = candB;
        unsigned* dst = candA;
        const int shifts4[4] = {21, 13, 5, 0};
        for (int pi = 0; pi < 4 && cc > RANK_MAX; pi++) {
            const int sh = shifts4[pi];
            for (int i = tid; i < 256; i += THREADS) hist[i] = 0u;
            if (tid == 0) s_cnt2 = 0;
            __syncthreads();
            for (int j = tid; j < cc; j += THREADS)
                atomicAdd(&hist[(src[j] >> sh) & 255u], 1u);
            __syncthreads();
            if (wid == 0) {
                int k = s_k;
                unsigned bins[8]; unsigned t = 0u;
#pragma unroll
                for (int i = 0; i < 8; i++) { bins[i] = hist[lane * 8 + i]; t += bins[i]; }
                unsigned s = t;
#pragma unroll
                for (int o = 1; o < 32; o <<= 1) {
                    unsigned u = __shfl_down_sync(0xffffffffu, s, o);
                    if (lane + o < 32) s += u;
                }
                unsigned above = s - t;      // count in strictly higher lanes
#pragma unroll
                for (int b = 7; b >= 0; b--) {
                    if (above < (unsigned)k && (unsigned)k <= above + bins[b]) {
                        s_sel = lane * 8 + b;
                        s_k   = k - (int)above;
                    }
                    above += bins[b];
                }
            }
            __syncthreads();
            const unsigned sel2 = (unsigned)s_sel;
            for (int j = tid; j < cc; j += THREADS) {
                unsigned key = src[j];
                unsigned d = (key >> sh) & 255u;
                if (d > sel2) {
                    double t = 1.0 + (double)key2f(key);
                    acc += t * t;
                } else if (d == sel2) {
                    int p = atomicAdd(&s_cnt2, 1);
                    dst[p] = key;
                }
            }
            __syncthreads();
            cc = s_cnt2;
            unsigned* tmp = src; src = dst; dst = tmp;
        }
        // ---------- Exact rank select (index tie-break; ties equal-valued)
        const int k = s_k;
        for (int j = tid; j < cc; j += THREADS) {
            unsigned mk = src[j];
            int r = 0;
            for (int t = 0; t < cc; t++) {
                unsigned o = src[t];
                r += (o > mk) || (o == mk && t < j);
            }
            if (r < k) {
                double t = 1.0 + (double)key2f(mk);
                acc += t * t;
            }
        }
    } else if (num_hard > 0) {
        // ---------- Exact fallback: full radix select over global row ------
        acc = 0.0;
        if (tid < 32) hist[tid] = 0u;
        __syncthreads();
        for (int col = tid; col < n; col += THREADS) {
            if (col == tgt) continue;
            unsigned key = f2key(__float_as_uint(__ldg(rowp + col)));
            atomicAdd(&hist[key >> 29], 1u);
        }
        __syncthreads();
        if (wid == 0) {
            int kk = num_hard;
            unsigned cc2 = (lane < 8) ? hist[lane] : 0u;
            unsigned s = cc2;
#pragma unroll
            for (int o = 1; o < 8; o <<= 1) {
                unsigned t = __shfl_down_sync(0xffffffffu, s, o);
                if (lane + o < 8) s += t;
            }
            unsigned above = s - cc2;
            if (lane < 8 && above < (unsigned)kk && (unsigned)kk <= s) {
                s_sel = (int)lane;
                s_k   = kk - (int)above;
            }
        }
        __syncthreads();
        unsigned pmask = 0xE0000000u;
        unsigned pval  = ((unsigned)s_sel) << 29;
        for (int col = tid; col < n; col += THREADS) {
            if (col == tgt) continue;
            unsigned key = f2key(__float_as_uint(__ldg(rowp + col)));
            if ((key >> 29) > (pval >> 29)) {
                double t = 1.0 + (double)key2f(key);
                acc += t * t;
            }
        }
        const int shifts[6] = {24, 19, 14, 9, 4, 0};
        for (int lv = 0; lv < 6; lv++) {
            const int sh = shifts[lv];
            const unsigned wmask = (lv == 5) ? 0xFu : 0x1Fu;
            if (tid < 32) hist[tid] = 0u;
            __syncthreads();
            for (int col = tid; col < n; col += THREADS) {
                if (col == tgt) continue;
                unsigned key = f2key(__float_as_uint(__ldg(rowp + col)));
                if ((key & pmask) == pval)
                    atomicAdd(&hist[(key >> sh) & wmask], 1u);
            }
            __syncthreads();
            if (wid == 0) {
                int kk = s_k;
                unsigned cc2 = hist[lane];
                unsigned s = cc2;
#pragma unroll
                for (int o = 1; o < 32; o <<= 1) {
                    unsigned t = __shfl_down_sync(0xffffffffu, s, o);
                    if (lane + o < 32) s += t;
                }
                unsigned above = s - cc2;
                if (above < (unsigned)kk && (unsigned)kk <= s) {
                    s_sel = (int)lane;
                    s_k   = kk - (int)above;
                }
            }
            __syncthreads();
            const unsigned dsel = (unsigned)s_sel;
            for (int col = tid; col < n; col += THREADS) {
                if (col == tgt) continue;
                unsigned key = f2key(__float_as_uint(__ldg(rowp + col)));
                if ((key & pmask) == pval && ((key >> sh) & wmask) > dsel) {
                    double t = 1.0 + (double)key2f(key);
                    acc += t * t;
                }
            }
            pval  |= dsel << sh;
            pmask |= wmask << sh;
            __syncthreads();
        }
        if (tid == 0) {      // remaining s_k elements equal pval exactly
            double t = 1.0 + (double)key2f(pval);
            acc += (double)s_k * t * t;
        }
    }

    // ---------- Block reduction (double) + per-row result ----------
#pragma unroll
    for (int o = 16; o > 0; o >>= 1)
        acc += __shfl_down_sync(0xffffffffu, acc, o);
    if (lane == 0) warp_sums[wid] = acc;
    __syncthreads();
    if (tid == 0) {
        double tot = 0.0;
#pragma unroll
        for (int w = 0; w < THREADS / 32; w++) tot += warp_sums[w];
        double d1 = 1.0 - (double)pos_val;
        double hard = (num_hard > 0) ? tot / (double)num_hard : 0.0;
        g_rows[row] = d1 * d1 + DELTA * hard;
    }
}

extern "C" void kernel_launch(void* const* d_in, const int* in_sizes, int n_in,
                              void* d_out, int out_size) {
    const float* inputs  = (const float*)d_in[0];
    const int*   targets = (const int*)d_in[1];
    int m = in_sizes[1];                    // rows (targets count)
    int n = in_sizes[0] / m;                // cols
    int num_hard = (int)(0.01 * (double)(n - 1));   // int(R*(n-1))
    if (m > MAXROWS) m = MAXROWS;           // safety (bench m = 4096)

    dtl_kernel<<<m, THREADS>>>(inputs, targets, n, num_hard);
    finalize_kernel<<<1, 256>>>((float*)d_out, m);
}